// round 13
// baseline (speedup 1.0000x reference)
#include <cuda_runtime.h>
#include <cuda_bf16.h>
#include <math.h>

#define NB 128
#define NC 32
#define HW 16
#define NE 4096
#define FSZ (NB*NC*HW*HW)   // 1048576
#define PVCAP (256*1024)

typedef unsigned long long u64;

static const int h_PNS[10] = {1,2,3,4,5,6,8,10,13,16};

// ---------------- scratch (device globals; no allocation) ----------------
__device__ float g_cbn[NE*NC];        // normalized codebook
__device__ float g_frest[FSZ];        // residual
__device__ float g_x[FSZ];            // tokens [ntok][32]
__device__ float g_pv[PVCAP];         // partial argmax values
__device__ int   g_pi[PVCAP];         // partial argmax indices
__device__ int   g_hist[NE];          // last-scale histogram
__device__ float g_part[10*2*NB];     // per (scale, block) sum of squares

__device__ __forceinline__ u64 ffma2(u64 a, u64 b, u64 c) {
    u64 d; asm("fma.rn.f32x2 %0, %1, %2, %3;" : "=l"(d) : "l"(a), "l"(b), "l"(c));
    return d;
}
__device__ __forceinline__ u64 fadd2(u64 a, u64 b) {
    u64 d; asm("add.rn.f32x2 %0, %1, %2;" : "=l"(d) : "l"(a), "l"(b));
    return d;
}
__device__ __forceinline__ u64 pack2(float lo, float hi) {
    u64 d; asm("mov.b64 %0, {%1, %2};" : "=l"(d) : "f"(lo), "f"(hi));
    return d;
}

// h_up stored channel-paired: float2[(c>>1)][pix] ; scalar element accessor:
#define HUPIDX(c, pix) (((c) >> 1) * 650 + (pix) * 2 + ((c) & 1))

// --- init: f_rest <- f_input, zero out/hist, normalize codebook, pn=1 tokens ---
__global__ void k_init(const float* __restrict__ fin, const float* __restrict__ cb,
                       float* __restrict__ out, int out_size) {
    int i = blockIdx.x * 256 + threadIdx.x;
    if (i < FSZ) g_frest[i] = fin[i];
    if (i < out_size) out[i] = 0.0f;
    if (i < NE) {
        g_hist[i] = 0;
        const float* r = cb + (size_t)i * NC;
        float s = 0.f;
#pragma unroll
        for (int c = 0; c < NC; c++) s += r[c] * r[c];
        float inv = 1.0f / fmaxf(sqrtf(s), 1e-12f);
        float* w = g_cbn + (size_t)i * NC;
#pragma unroll
        for (int c = 0; c < NC; c++) w[c] = r[c] * inv;
    }
    // pn=1 tokens: g_x[b*32+c] = mean over 256 pixels of fin[b][c]
    if (i < NB * NC) {
        const float* base = fin + (size_t)i * 256;
        float s = 0.f;
        for (int p = 0; p < 256; p++) s += base[p];
        g_x[i] = s * (1.0f / 256.0f);
    }
}

// ---------------- argmax: smem-tiled, T tokens per thread, f32x2 packed ----------
// grid = (ceil(ntok/(128*T)), CS), block = 128. cpb = 4096/CS (multiple of 128).
// pn16 != 0: read tokens transposed from g_frest (last scale).
template<int T>
__global__ __launch_bounds__(128) void k_argmax_t(int ntok, int cpb, int pn16) {
    __shared__ float s_cb[128 * NC];
    int tid = threadIdx.x;
    int cbase = blockIdx.y * cpb;
    int tokbase = blockIdx.x * (128 * T) + tid;

    u64 tk[T][16];
    float bv[T]; int bi[T]; bool vld[T];
#pragma unroll
    for (int t = 0; t < T; t++) {
        int tok = tokbase + t * 128;
        vld[t] = tok < ntok;
        bv[t] = -3.4e38f; bi[t] = cbase;
#pragma unroll
        for (int i = 0; i < 16; i++) tk[t][i] = 0ULL;
        if (vld[t]) {
            if (pn16) {
                int b = tok >> 8, pix = tok & 255;
                const float* fr = g_frest + (size_t)b * 8192 + pix;
#pragma unroll
                for (int i = 0; i < 16; i++) {
                    float2 v;
                    v.x = fr[(2 * i) * 256];
                    v.y = fr[(2 * i + 1) * 256];
                    tk[t][i] = *(u64*)&v;
                }
            } else {
                const ulonglong2* p = (const ulonglong2*)(g_x + (size_t)tok * NC);
#pragma unroll
                for (int i = 0; i < 8; i++) {
                    ulonglong2 v = p[i];
                    tk[t][2 * i] = v.x; tk[t][2 * i + 1] = v.y;
                }
            }
        }
    }

    for (int tile = 0; tile < cpb; tile += 128) {
        __syncthreads();
        {
            const float4* src = (const float4*)(g_cbn + (size_t)(cbase + tile) * NC);
            float4* dst = (float4*)s_cb;
#pragma unroll
            for (int i = 0; i < 8; i++) dst[tid + i * 128] = src[tid + i * 128];
        }
        __syncthreads();
        for (int j = 0; j < 128; j++) {
            const ulonglong2* cr = (const ulonglong2*)(s_cb + j * NC);
            u64 c[16];
#pragma unroll
            for (int i = 0; i < 8; i++) {
                ulonglong2 v = cr[i];
                c[2 * i] = v.x; c[2 * i + 1] = v.y;
            }
            int code = cbase + tile + j;
#pragma unroll
            for (int t = 0; t < T; t++) {
                u64 p0 = 0ULL, p1 = 0ULL;
#pragma unroll
                for (int i = 0; i < 8; i++) {
                    p0 = ffma2(c[2 * i],     tk[t][2 * i],     p0);
                    p1 = ffma2(c[2 * i + 1], tk[t][2 * i + 1], p1);
                }
                u64 ps = fadd2(p0, p1);
                float2 pf = *(float2*)&ps;
                float d = pf.x + pf.y;
                if (d > bv[t]) { bv[t] = d; bi[t] = code; }
            }
        }
    }
    int CS = gridDim.y, cs = blockIdx.y;
#pragma unroll
    for (int t = 0; t < T; t++) {
        int tok = tokbase + t * 128;
        if (vld[t]) {
            g_pv[(size_t)tok * CS + cs] = bv[t];
            g_pi[(size_t)tok * CS + cs] = bi[t];
        }
    }
}

// -------- fused: combine -> gather -> bicubic up -> 3x3 conv (16 co, f32x2
//          channel-paired) -> update -> next-scale tokens.
//          grid = 2*NB (2 blocks per image), 256 threads.
#define SW_OFF   0                    // 4608 : this block's 16 co of phi weights
#define SB_OFF   4608                 // 32
#define HUP_OFF  4640                 // 10400 : halo'd h_up, float2[(c/2)][325]
#define HS_OFF   15040                // 8192  : gathered codes [p][c]
#define WT_OFF   23232                // 64
#define JT_OFF   23296                // 64
#define RED_OFF  23360                // 16
#define IDX_OFF  23376                // 256
#define SMEM_FLOATS 23632             // 94528 bytes -> 2 blocks/SM

__global__ __launch_bounds__(256) void k_fused(
    const float* __restrict__ fin, float* __restrict__ fhat,
    const float* __restrict__ cb, const float* __restrict__ phiw,
    const float* __restrict__ phib, int si, int pn, int k, int last, int CS,
    int next_pn) {
    extern __shared__ float sm[];
    float* s_w   = sm + SW_OFF;
    float* s_b   = sm + SB_OFF;
    float* s_hup = sm + HUP_OFF;      // scalar view (HUPIDX)
    float2* hup2 = (float2*)(sm + HUP_OFF);
    float* s_hs  = sm + HS_OFF;
    float* s_wt  = sm + WT_OFF;
    int*   s_jt  = (int*)(sm + JT_OFF);
    float* s_red = sm + RED_OFF;
    int*   s_idx = (int*)(sm + IDX_OFF);

    int tid = threadIdx.x;
    int bx = blockIdx.x;
    int b = bx >> 1, half = bx & 1;
    int c0 = half * 16;               // this block's output-channel base
    int pnpn = pn * pn;

    // combine code-split argmax partials (+ histogram from half-0 only)
    for (int p = tid; p < pnpn; p += 256) {
        size_t tb = (size_t)(b * pnpn + p) * CS;
        float bvv = g_pv[tb]; int bii = g_pi[tb];
        for (int cs = 1; cs < CS; cs++) {
            float v = g_pv[tb + cs]; int i2 = g_pi[tb + cs];
            if (v > bvv || (v == bvv && i2 < bii)) { bvv = v; bii = i2; }
        }
        s_idx[p] = bii;
        if (last && half == 0) atomicAdd(&g_hist[bii], 1);
    }

    // load this block's 16 co of Phi weights (+ all 32 biases)
    {
        const float4* wsrc = (const float4*)(phiw + (size_t)k * 9216 + c0 * 288);
        float4* wdst = (float4*)s_w;
        for (int i = tid; i < 1152; i += 256) wdst[i] = wsrc[i];
        if (tid < 32) s_b[tid] = phib[k * 32 + tid];
    }
    for (int i = tid; i < 10400; i += 256) s_hup[i] = 0.f;

    if (!last && tid < 64) {
        int i = tid >> 2, off = (tid & 3) - 1;
        double src = (i + 0.5) * (double)pn / 16.0 - 0.5;
        double i0 = floor(src);
        double f = src - i0;
        double t = fabs(f - (double)off);
        double w;
        if (t <= 1.0)      w = (1.25 * t - 2.25) * t * t + 1.0;
        else if (t < 2.0)  w = (((t - 5.0) * t + 8.0) * t - 4.0) * (-0.75);
        else               w = 0.0;
        int j = (int)i0 + off;
        j = min(max(j, 0), pn - 1);
        s_wt[tid] = (float)w;
        s_jt[tid] = j;
    }
    __syncthreads();

    if (!last) {
        for (int t = tid; t < pnpn * 32; t += 256) {
            int p = t >> 5, c = t & 31;
            s_hs[t] = cb[(size_t)s_idx[p] * NC + c];
        }
        __syncthreads();
    }

    // build h_up (interior of halo'd image), all 32 channels
    if (last) {
        for (int o = tid; o < 8192; o += 256) {
            int c = o & 31, pix = o >> 5;
            int y = pix >> 4, x = pix & 15;
            s_hup[HUPIDX(c, (y + 1) * 18 + (x + 1))] =
                cb[(size_t)s_idx[pix] * NC + c];
        }
    } else {
        for (int o = tid; o < 8192; o += 256) {
            int c = o & 31, pix = o >> 5;
            int y = pix >> 4, x = pix & 15;
            float acc = 0.f;
#pragma unroll
            for (int ty = 0; ty < 4; ty++) {
                float wy = s_wt[y * 4 + ty];
                int jy = s_jt[y * 4 + ty];
                const float* row = s_hs + (jy * pn) * 32 + c;
                float rs = 0.f;
#pragma unroll
                for (int tx = 0; tx < 4; tx++)
                    rs = fmaf(s_wt[x * 4 + tx], row[s_jt[x * 4 + tx] * 32], rs);
                acc = fmaf(wy, rs, acc);
            }
            s_hup[HUPIDX(c, (y + 1) * 18 + (x + 1))] = acc;
        }
    }
    __syncthreads();

    // 3x3 conv, channel-paired f32x2: warp wi (0..7) owns co = c0 + 2wi + co2;
    // lane -> (y = lane>>1, xs = (lane&1)*8).  acc2 lanes = (even ci, odd ci).
    int wi = tid >> 5, lane = tid & 31;
    int y = lane >> 1, xs = (lane & 1) * 8;
    u64 acc2[2][8];
#pragma unroll
    for (int a = 0; a < 2; a++)
#pragma unroll
        for (int o = 0; o < 8; o++) acc2[a][o] = 0ULL;

    for (int ci2 = 0; ci2 < 16; ci2++) {
        const float2* hp = hup2 + ci2 * 325 + y * 18 + xs;
        const float* wp0 = s_w + ((size_t)(wi * 2 + 0) * 32 + 2 * ci2) * 9;
        const float* wp1 = s_w + ((size_t)(wi * 2 + 1) * 32 + 2 * ci2) * 9;
#pragma unroll
        for (int r = 0; r < 3; r++) {
            u64 row[10];
#pragma unroll
            for (int cc = 0; cc < 10; cc++) {
                float2 v = hp[r * 18 + cc];
                row[cc] = *(u64*)&v;
            }
#pragma unroll
            for (int co2 = 0; co2 < 2; co2++) {
                const float* wp = co2 ? wp1 : wp0;
#pragma unroll
                for (int t = 0; t < 3; t++) {
                    u64 wt = pack2(wp[r * 3 + t], wp[r * 3 + t + 9]);
#pragma unroll
                    for (int xo = 0; xo < 8; xo++)
                        acc2[co2][xo] = ffma2(wt, row[xo + t], acc2[co2][xo]);
                }
            }
        }
    }

    // h = 0.5*h_up + 0.5*(conv + bias); update f_hat, f_rest; accumulate MSE
    float sq = 0.f;
    const float* finb = fin + (size_t)b * 8192;
    float* fhb = fhat + (size_t)b * 8192;
    float* frb = g_frest + (size_t)b * 8192;
#pragma unroll
    for (int co2 = 0; co2 < 2; co2++) {
        int co = c0 + wi * 2 + co2;
        float bias = s_b[co];
#pragma unroll
        for (int xo = 0; xo < 8; xo++) {
            int x = xs + xo;
            float2 a2 = *(float2*)&acc2[co2][xo];
            float conv = (a2.x + a2.y) + bias;
            float hu = s_hup[HUPIDX(co, (y + 1) * 18 + (x + 1))];
            float h = 0.5f * hu + 0.5f * conv;
            int g = co * 256 + y * 16 + x;
            float fh = fhb[g] + h;
            fhb[g] = fh;
            frb[g] = frb[g] - h;
            float d = fh - finb[g];
            sq = fmaf(d, d, sq);
        }
    }
#pragma unroll
    for (int o = 16; o; o >>= 1) sq += __shfl_down_sync(0xffffffffu, sq, o);
    if (lane == 0) s_red[wi] = sq;
    __syncthreads();
    if (tid == 0) {
        float s = 0.f;
        for (int i = 0; i < 8; i++) s += s_red[i];
        g_part[si * 2 * NB + bx] = s;
    }

    // tail: next-scale tokens for this block's 16 channels (f_rest just updated)
    if (next_pn) {
        int npp = next_pn * next_pn;
        for (int t = tid; t < npp * 16; t += 256) {
            int cl = t & 15, p = t >> 4;
            int c = c0 + cl;
            int py = p / next_pn, px = p - py * next_pn;
            int ys = (py * HW) / next_pn, ye = ((py + 1) * HW + next_pn - 1) / next_pn;
            int xs2 = (px * HW) / next_pn, xe = ((px + 1) * HW + next_pn - 1) / next_pn;
            const float* bc = frb + c * 256;
            float s = 0.f;
            for (int yy = ys; yy < ye; yy++)
                for (int xx = xs2; xx < xe; xx++) s += bc[yy * 16 + xx];
            g_x[(size_t)(b * npp + p) * NC + c] =
                s / (float)((ye - ys) * (xe - xs2));
        }
    }
}

// ---------------- finalize: loss + perplexity ----------------
__global__ void k_final(float* __restrict__ out, int out_size) {
    __shared__ float sr[256];
    int tid = threadIdx.x;
    float s = 0.f;
    for (int i = tid; i < 10 * 2 * NB; i += 256) s += g_part[i];
    sr[tid] = s;
    __syncthreads();
    for (int o = 128; o; o >>= 1) {
        if (tid < o) sr[tid] += sr[tid + o];
        __syncthreads();
    }
    float lossv = 0.f;
    if (tid == 0) lossv = sr[0] * (1.25f / (10.0f * (float)FSZ));
    __syncthreads();

    float e = 0.f;
    for (int i = tid; i < NE; i += 256) {
        float p = (float)g_hist[i] * (1.0f / 32768.0f);
        e += p * logf(p + 1e-10f);
    }
    sr[tid] = e;
    __syncthreads();
    for (int o = 128; o; o >>= 1) {
        if (tid < o) sr[tid] += sr[tid + o];
        __syncthreads();
    }
    if (tid == 0) {
        out[out_size - 2] = lossv;
        out[out_size - 1] = expf(-sr[0]);
    }
}

// ---------------- launcher ----------------
extern "C" void kernel_launch(void* const* d_in, const int* in_sizes, int n_in,
                              void* d_out, int out_size) {
    // Identify inputs BY SIZE (robust to metadata ordering).
    const float* fin  = nullptr;
    const float* cb   = nullptr;
    const float* phiw = nullptr;
    const float* phib = nullptr;
    for (int i = 0; i < n_in; i++) {
        int sz = in_sizes[i];
        if      (sz == FSZ)        fin  = (const float*)d_in[i];
        else if (sz == NE * NC)    cb   = (const float*)d_in[i];
        else if (sz == 4*NC*NC*9)  phiw = (const float*)d_in[i];
        else if (sz == 4*NC)       phib = (const float*)d_in[i];
    }
    float* out = (float*)d_out;

    // PhiPartiallyShared tick schedule, replicating numpy float64 exactly.
    int phik[10];
    {
        double start = 1.0 / 12.0;
        double stop  = 1.0 - 1.0 / 12.0;
        double step  = (stop - start) / 3.0;
        double ticks[4];
        ticks[0] = start;
        ticks[1] = 1.0 * step + start;
        ticks[2] = 2.0 * step + start;
        ticks[3] = stop;
        for (int si = 0; si < 10; si++) {
            double v = (double)si / 9.0;
            int best = 0;
            double bd = fabs(ticks[0] - v);
            for (int kk = 1; kk < 4; kk++) {
                double d = fabs(ticks[kk] - v);
                if (d < bd) { bd = d; best = kk; }
            }
            phik[si] = best;
        }
    }

    cudaFuncSetAttribute(k_fused, cudaFuncAttributeMaxDynamicSharedMemorySize,
                         SMEM_FLOATS * 4);

    int initN = (FSZ > out_size ? FSZ : out_size);
    k_init<<<(initN + 255) / 256, 256>>>(fin, cb, out, out_size);

    for (int si = 0; si < 10; si++) {
        int pn = h_PNS[si];
        int ntok = NB * pn * pn;
        int last = (si == 9);
        int next_pn = (si < 8) ? h_PNS[si + 1] : 0;   // pn16 reads g_frest directly

        int CS;
        if (ntok >= 2048) {
            int tb = (ntok + 511) / 512;
            CS = 1;
            while (tb * CS < 296 && CS < 32) CS <<= 1;
            dim3 g(tb, CS);
            k_argmax_t<4><<<g, 128>>>(ntok, NE / CS, last ? 1 : 0);
        } else {
            int tb = ntok / 128;
            CS = 1;
            while (tb * CS < 296 && CS < 32) CS <<= 1;
            dim3 g(tb, CS);
            k_argmax_t<1><<<g, 128>>>(ntok, NE / CS, 0);
        }

        k_fused<<<2 * NB, 256, SMEM_FLOATS * 4>>>(fin, out, cb, phiw, phib,
                                                  si, pn, phik[si], last, CS,
                                                  next_pn);
    }
    k_final<<<1, 256>>>(out, out_size);
}